// round 2
// baseline (speedup 1.0000x reference)
#include <cuda_runtime.h>
#include <cuda_bf16.h>

// Problem constants (S=8192, G=1024, T=4096, E=16384)
#define E_N 16384
#define T_N 4096
#define G_N 1024
#define CHUNK 32
#define NCHUNKS (T_N / CHUNK)   // 128
#define LIST_CAP 8192           // per-chunk boundary-event capacity (exp ~250)

// Chunk-granularity difference array and its prefix (carry at each chunk start).
__device__ float g_cdiff[NCHUNKS * G_N];   // zero-init at load; re-zeroed by K2
__device__ float g_carry[NCHUNKS * G_N];
// Per-chunk boundary-event lists: {row<<10 | group, w_bits}
__device__ int2  g_list[NCHUNKS * LIST_CAP];
__device__ int   g_count[NCHUNKS];         // zero-init; re-zeroed by K3

// ---------------------------------------------------------------------------
// K1: per-event preprocess + binning.
//   ts = lower_bound(t0, start), te = lower_bound(t0, end) -> active rows [ts,te)
//   Chunk-level: +w at cdiff[ceil(ts/32)], -w at cdiff[ceil(te/32)]
//   Row-level:   interior boundaries (ts%32!=0 / te%32!=0) go to per-chunk lists
// ---------------------------------------------------------------------------
__global__ void preprocess_kernel(const int*   __restrict__ index,
                                  const float* __restrict__ rate,
                                  const float* __restrict__ start,
                                  const float* __restrict__ endt,
                                  const float* __restrict__ t0,
                                  const int*   __restrict__ group_id,
                                  const float* __restrict__ weights) {
    __shared__ float s_t0[T_N];  // 16 KB
    for (int i = threadIdx.x; i < T_N; i += blockDim.x) s_t0[i] = t0[i];
    __syncthreads();

    int e = blockIdx.x * blockDim.x + threadIdx.x;
    if (e >= E_N) return;

    float st = start[e];
    float en = endt[e];

    int lo = 0, hi = T_N;
    #pragma unroll 1
    while (lo < hi) { int mid = (lo + hi) >> 1; if (s_t0[mid] < st) lo = mid + 1; else hi = mid; }
    const int ts = lo;

    lo = 0; hi = T_N;
    #pragma unroll 1
    while (lo < hi) { int mid = (lo + hi) >> 1; if (s_t0[mid] < en) lo = mid + 1; else hi = mid; }
    const int te = lo;

    if (te <= ts) return;  // never active

    const int src = index[e];
    const float w = rate[e] * weights[src];
    const int g = group_id[src];

    // chunk-level diff (skip if both boundaries in same chunk: they cancel)
    const int c0 = (ts + CHUNK - 1) >> 5;
    const int c1 = (te + CHUNK - 1) >> 5;
    if (c0 != c1) {
        if (c0 < NCHUNKS) atomicAdd(&g_cdiff[c0 * G_N + g],  w);
        if (c1 < NCHUNKS) atomicAdd(&g_cdiff[c1 * G_N + g], -w);
    }

    // interior row-level boundaries
    const int rs = ts & (CHUNK - 1);
    if (rs != 0) {  // ts < T_N guaranteed (ts<te<=T_N, rs!=0 => ts not T_N)
        int idx = atomicAdd(&g_count[ts >> 5], 1);
        if (idx < LIST_CAP)
            g_list[(ts >> 5) * LIST_CAP + idx] =
                make_int2((rs << 10) | g, __float_as_int(w));
    }
    const int re = te & (CHUNK - 1);
    if (re != 0 && te < T_N) {
        int idx = atomicAdd(&g_count[te >> 5], 1);
        if (idx < LIST_CAP)
            g_list[(te >> 5) * LIST_CAP + idx] =
                make_int2((re << 10) | g, __float_as_int(-w));
    }
}

// ---------------------------------------------------------------------------
// K2: prefix-scan cdiff along chunks -> carry; zero cdiff behind the read so
// the next graph replay sees a clean buffer. 32 blocks x 32 threads, each
// thread owns one group column; loads/stores fully coalesced per warp.
// ---------------------------------------------------------------------------
__global__ void chunk_scan_kernel() {
    const int g = blockIdx.x * 32 + threadIdx.x;
    float acc = 0.0f;
    #pragma unroll 8
    for (int c = 0; c < NCHUNKS; c++) {
        acc += g_cdiff[c * G_N + g];
        g_carry[c * G_N + g] = acc;
        g_cdiff[c * G_N + g] = 0.0f;
    }
}

// ---------------------------------------------------------------------------
// K3: one block per chunk. Scatter the ~250 boundary entries into a 32x1024
// smem diff tile, then per-group serial prefix (base = carry) + coalesced STG.
// ---------------------------------------------------------------------------
__global__ void __launch_bounds__(G_N, 1)
chunk_emit_kernel(float* __restrict__ out) {
    extern __shared__ float diff[];  // CHUNK * G_N floats = 128 KB
    const int cblk = blockIdx.x;
    const int tid  = threadIdx.x;
    const int tbeg = cblk * CHUNK;

    int n = g_count[cblk];
    n = n < LIST_CAP ? n : LIST_CAP;

    #pragma unroll
    for (int r = 0; r < CHUNK; r++)
        diff[r * G_N + tid] = 0.0f;
    __syncthreads();

    for (int i = tid; i < n; i += G_N) {
        int2 ev = g_list[cblk * LIST_CAP + i];
        atomicAdd(&diff[(ev.x >> 10) * G_N + (ev.x & (G_N - 1))],
                  __int_as_float(ev.y));
    }
    __syncthreads();

    float acc = g_carry[cblk * G_N + tid];
    #pragma unroll
    for (int r = 0; r < CHUNK; r++) {
        acc += diff[r * G_N + tid];          // row 0 is always 0
        out[(size_t)(tbeg + r) * G_N + tid] = acc;
    }

    __syncthreads();
    if (tid == 0) g_count[cblk] = 0;  // clean for next replay
}

// ---------------------------------------------------------------------------
extern "C" void kernel_launch(void* const* d_in, const int* in_sizes, int n_in,
                              void* d_out, int out_size) {
    const int*   index    = (const int*)  d_in[0];
    const float* rate     = (const float*)d_in[1];
    const float* start    = (const float*)d_in[2];
    const float* endt     = (const float*)d_in[3];
    const float* t0       = (const float*)d_in[4];
    const int*   group_id = (const int*)  d_in[5];
    const float* weights  = (const float*)d_in[6];
    float* out = (float*)d_out;

    cudaFuncSetAttribute(chunk_emit_kernel,
                         cudaFuncAttributeMaxDynamicSharedMemorySize,
                         CHUNK * G_N * (int)sizeof(float));

    preprocess_kernel<<<E_N / 256, 256>>>(index, rate, start, endt, t0,
                                          group_id, weights);
    chunk_scan_kernel<<<G_N / 32, 32>>>();
    chunk_emit_kernel<<<NCHUNKS, G_N, CHUNK * G_N * (int)sizeof(float)>>>(out);
}

// round 3
// speedup vs baseline: 1.6363x; 1.6363x over previous
#include <cuda_runtime.h>
#include <cuda_bf16.h>

// Problem constants (S=8192, G=1024, T=4096, E=16384)
#define E_N 16384
#define T_N 4096
#define G_N 1024
#define CHUNK 32
#define NCHUNKS (T_N / CHUNK)   // 128
#define LIST_CAP 8192           // per-chunk boundary capacity (expected ~250)

// Chunk-granularity difference array and its prefix (carry at chunk starts).
__device__ float g_cdiff[NCHUNKS * G_N];   // zeroed at load; re-zeroed by K2
__device__ float g_carry[NCHUNKS * G_N];
// Per-chunk boundary-event lists: {row<<10 | group, w_bits}
__device__ int2  g_list[NCHUNKS * LIST_CAP];
__device__ int   g_count[NCHUNKS];         // zeroed at load; re-zeroed by K3

// ---------------------------------------------------------------------------
// K1: per-event preprocess + binning. Branchless lower_bound, both searches
// interleaved (2 independent load chains). t0 (16 KB) stays L1-resident.
// ---------------------------------------------------------------------------
__global__ void __launch_bounds__(128)
preprocess_kernel(const int*   __restrict__ index,
                  const float* __restrict__ rate,
                  const float* __restrict__ start,
                  const float* __restrict__ endt,
                  const float* __restrict__ t0,
                  const int*   __restrict__ group_id,
                  const float* __restrict__ weights) {
    const int e = blockIdx.x * 128 + threadIdx.x;

    const float st = __ldg(&start[e]);
    const float en = __ldg(&endt[e]);

    // Branchless lower_bound over sorted t0 (size 4096 = 2^12).
    // Invariant: all elements before lo are < key. Fixup handles lb == T_N.
    int a = 0, b = 0;
    #pragma unroll
    for (int s = T_N >> 1; s; s >>= 1) {
        a += (__ldg(&t0[a + s - 1]) < st) ? s : 0;
        b += (__ldg(&t0[b + s - 1]) < en) ? s : 0;
    }
    a += (__ldg(&t0[a]) < st) ? 1 : 0;   // ts
    b += (__ldg(&t0[b]) < en) ? 1 : 0;   // te

    const int ts = a, te = b;
    if (te <= ts) return;  // never active

    const int src = __ldg(&index[e]);
    const float w = __ldg(&rate[e]) * __ldg(&weights[src]);
    const int g = __ldg(&group_id[src]);

    // Chunk-level diff: +w at first fully-covered chunk, -w at first
    // uncovered chunk (fire-and-forget REDG, spread addresses).
    const int c0 = (ts + CHUNK - 1) >> 5;
    const int c1 = (te + CHUNK - 1) >> 5;
    if (c0 != c1) {
        if (c0 < NCHUNKS) atomicAdd(&g_cdiff[c0 * G_N + g],  w);
        if (c1 < NCHUNKS) atomicAdd(&g_cdiff[c1 * G_N + g], -w);
    }

    // Interior row-level boundaries -> per-chunk lists (two independent
    // ATOMG-return chains; issued back-to-back).
    const int rs = ts & (CHUNK - 1);
    const int re = te & (CHUNK - 1);
    if (rs != 0) {
        int idx = atomicAdd(&g_count[ts >> 5], 1);
        if (idx < LIST_CAP)
            g_list[(ts >> 5) * LIST_CAP + idx] =
                make_int2((rs << 10) | g, __float_as_int(w));
    }
    if (re != 0 && te < T_N) {
        int idx = atomicAdd(&g_count[te >> 5], 1);
        if (idx < LIST_CAP)
            g_list[(te >> 5) * LIST_CAP + idx] =
                make_int2((re << 10) | g, __float_as_int(-w));
    }
}

// ---------------------------------------------------------------------------
// K2: prefix-scan cdiff along chunks -> carry; zero cdiff behind the read.
// Register-batched: 16 loads in flight per thread, then the FADD/STG tail.
// 1024 threads (one per group column), coalesced per warp.
// ---------------------------------------------------------------------------
__global__ void __launch_bounds__(128)
chunk_scan_kernel() {
    const int g = blockIdx.x * 128 + threadIdx.x;  // 8 blocks x 128 = 1024
    float acc = 0.0f;
    float v[16];
    #pragma unroll 1
    for (int b = 0; b < NCHUNKS / 16; b++) {
        #pragma unroll
        for (int i = 0; i < 16; i++)
            v[i] = g_cdiff[(b * 16 + i) * G_N + g];
        #pragma unroll
        for (int i = 0; i < 16; i++) {
            acc += v[i];
            g_carry[(b * 16 + i) * G_N + g] = acc;
            g_cdiff[(b * 16 + i) * G_N + g] = 0.0f;
        }
    }
}

// ---------------------------------------------------------------------------
// K3: one block per chunk. Scatter ~250 boundary entries into a 32x1024 smem
// diff tile, then per-group serial prefix (base = carry) + coalesced STG.
// ---------------------------------------------------------------------------
__global__ void __launch_bounds__(G_N, 1)
chunk_emit_kernel(float* __restrict__ out) {
    extern __shared__ float diff[];  // CHUNK * G_N floats = 128 KB
    const int cblk = blockIdx.x;
    const int tid  = threadIdx.x;
    const int tbeg = cblk * CHUNK;

    int n = g_count[cblk];
    n = n < LIST_CAP ? n : LIST_CAP;

    // Vectorized zero: 8192 float4 / 1024 threads = 8 each
    float4* d4 = (float4*)diff;
    const float4 z = make_float4(0.f, 0.f, 0.f, 0.f);
    #pragma unroll
    for (int i = 0; i < (CHUNK * G_N / 4) / G_N; i++)
        d4[i * G_N + tid] = z;
    __syncthreads();

    for (int i = tid; i < n; i += G_N) {
        int2 ev = g_list[cblk * LIST_CAP + i];
        atomicAdd(&diff[(ev.x >> 10) * G_N + (ev.x & (G_N - 1))],
                  __int_as_float(ev.y));
    }
    __syncthreads();

    float acc = g_carry[cblk * G_N + tid];
    #pragma unroll
    for (int r = 0; r < CHUNK; r++) {
        acc += diff[r * G_N + tid];          // row 0 is always 0
        out[(size_t)(tbeg + r) * G_N + tid] = acc;
    }

    __syncthreads();
    if (tid == 0) g_count[cblk] = 0;  // clean for next replay
}

// ---------------------------------------------------------------------------
extern "C" void kernel_launch(void* const* d_in, const int* in_sizes, int n_in,
                              void* d_out, int out_size) {
    const int*   index    = (const int*)  d_in[0];
    const float* rate     = (const float*)d_in[1];
    const float* start    = (const float*)d_in[2];
    const float* endt     = (const float*)d_in[3];
    const float* t0       = (const float*)d_in[4];
    const int*   group_id = (const int*)  d_in[5];
    const float* weights  = (const float*)d_in[6];
    float* out = (float*)d_out;

    cudaFuncSetAttribute(chunk_emit_kernel,
                         cudaFuncAttributeMaxDynamicSharedMemorySize,
                         CHUNK * G_N * (int)sizeof(float));

    preprocess_kernel<<<E_N / 128, 128>>>(index, rate, start, endt, t0,
                                          group_id, weights);
    chunk_scan_kernel<<<G_N / 128, 128>>>();
    chunk_emit_kernel<<<NCHUNKS, G_N, CHUNK * G_N * (int)sizeof(float)>>>(out);
}

// round 4
// speedup vs baseline: 2.2431x; 1.3708x over previous
#include <cuda_runtime.h>
#include <cuda_bf16.h>

// Problem constants (S=8192, G=1024, T=4096, E=16384)
#define E_N 16384
#define T_N 4096
#define G_N 1024
#define CHUNK 32
#define NCHUNKS (T_N / CHUNK)   // 128
#define NSUB 8                  // sub-counters per chunk (atomic spread)
#define SUBCAP 1024             // capacity per sub-list (expected ~30)

// cdiff TRANSPOSED: [group][chunk] so K2 loads are per-thread contiguous.
__device__ float g_cdiff[G_N * NCHUNKS];     // zeroed at load; re-zeroed by K2
// carry: [chunk][group] so K3 reads are warp-coalesced.
__device__ float g_carry[NCHUNKS * G_N];
// Per-(chunk,sub) boundary lists: {row<<10 | group, w_bits}
__device__ int2  g_list[NCHUNKS * NSUB * SUBCAP];
__device__ int   g_count[NCHUNKS * NSUB];    // zeroed at load; re-zeroed by K3

// ---------------------------------------------------------------------------
// K1: per-event preprocess + binning.
// smem t0 (L1 is flushed per launch -> gmem search would be L2-latency-bound),
// branchless interleaved lower_bound, scalar loads hoisted above the search,
// 8-way split chunk counters to kill ATOMG serialization.
// ---------------------------------------------------------------------------
__global__ void __launch_bounds__(128)
preprocess_kernel(const int*   __restrict__ index,
                  const float* __restrict__ rate,
                  const float* __restrict__ start,
                  const float* __restrict__ endt,
                  const float* __restrict__ t0,
                  const int*   __restrict__ group_id,
                  const float* __restrict__ weights) {
    __shared__ float s_t0[T_N];  // 16 KB
    {
        float4* s4 = (float4*)s_t0;
        const float4* t4 = (const float4*)t0;
        #pragma unroll
        for (int i = 0; i < T_N / 4 / 128; i++)      // 8 x float4 per thread
            s4[i * 128 + threadIdx.x] = t4[i * 128 + threadIdx.x];
    }

    const int e = blockIdx.x * 128 + threadIdx.x;

    // All global scalar loads issued before the search (overlap with sync+LDS).
    const float st = __ldg(&start[e]);
    const float en = __ldg(&endt[e]);
    const int   src = __ldg(&index[e]);
    const float rt  = __ldg(&rate[e]);
    const float wsc = __ldg(&weights[src]);
    const int   g   = __ldg(&group_id[src]);

    __syncthreads();

    // Branchless lower_bound over sorted t0 (4096 = 2^12), both keys
    // interleaved -> two independent LDS chains.
    int a = 0, b = 0;
    #pragma unroll
    for (int s = T_N >> 1; s; s >>= 1) {
        a += (s_t0[a + s - 1] < st) ? s : 0;
        b += (s_t0[b + s - 1] < en) ? s : 0;
    }
    a += (s_t0[a] < st) ? 1 : 0;   // ts = lower_bound(t0, st)
    b += (s_t0[b] < en) ? 1 : 0;   // te = lower_bound(t0, en)

    const int ts = a, te = b;
    if (te <= ts) return;  // never active

    const float w = rt * wsc;

    // Chunk-level diff (transposed layout), fire-and-forget REDG.
    const int c0 = (ts + CHUNK - 1) >> 5;
    const int c1 = (te + CHUNK - 1) >> 5;
    if (c0 != c1) {
        if (c0 < NCHUNKS) atomicAdd(&g_cdiff[g * NCHUNKS + c0],  w);
        if (c1 < NCHUNKS) atomicAdd(&g_cdiff[g * NCHUNKS + c1], -w);
    }

    // Interior row-level boundaries -> split sub-lists (8x less contention).
    const int sub = e & (NSUB - 1);
    const int rs = ts & (CHUNK - 1);
    const int re = te & (CHUNK - 1);
    if (rs != 0) {
        const int bin = (ts >> 5) * NSUB + sub;
        int idx = atomicAdd(&g_count[bin], 1);
        if (idx < SUBCAP)
            g_list[bin * SUBCAP + idx] = make_int2((rs << 10) | g,
                                                   __float_as_int(w));
    }
    if (re != 0 && te < T_N) {
        const int bin = (te >> 5) * NSUB + sub;
        int idx = atomicAdd(&g_count[bin], 1);
        if (idx < SUBCAP)
            g_list[bin * SUBCAP + idx] = make_int2((re << 10) | g,
                                                   __float_as_int(-w));
    }
}

// ---------------------------------------------------------------------------
// K2: per-group prefix over chunks. cdiff row is contiguous per thread
// (transposed layout): 8x LDG.128 in flight per batch. Zero cdiff behind the
// read; store carry[chunk][group] (warp-coalesced: lanes = consecutive g).
// ---------------------------------------------------------------------------
__global__ void __launch_bounds__(64)
chunk_scan_kernel() {
    const int g = blockIdx.x * 64 + threadIdx.x;  // 16 blocks x 64 = 1024
    float4* row = (float4*)&g_cdiff[g * NCHUNKS];
    const float4 z = make_float4(0.f, 0.f, 0.f, 0.f);
    float acc = 0.0f;
    #pragma unroll
    for (int bt = 0; bt < 4; bt++) {              // 4 batches of 32 chunks
        float4 v[8];
        #pragma unroll
        for (int i = 0; i < 8; i++) v[i] = row[bt * 8 + i];
        #pragma unroll
        for (int i = 0; i < 8; i++) {
            const int c = bt * 32 + i * 4;
            acc += v[i].x; g_carry[(c + 0) * G_N + g] = acc;
            acc += v[i].y; g_carry[(c + 1) * G_N + g] = acc;
            acc += v[i].z; g_carry[(c + 2) * G_N + g] = acc;
            acc += v[i].w; g_carry[(c + 3) * G_N + g] = acc;
        }
        #pragma unroll
        for (int i = 0; i < 8; i++) row[bt * 8 + i] = z;
    }
}

// ---------------------------------------------------------------------------
// K3: one block per chunk. Scatter its ~250 boundary entries (8 sub-lists)
// into a 32x1024 smem diff tile, then per-group serial prefix (base = carry)
// + coalesced STG.
// ---------------------------------------------------------------------------
__global__ void __launch_bounds__(G_N, 1)
chunk_emit_kernel(float* __restrict__ out) {
    extern __shared__ float diff[];  // CHUNK * G_N floats = 128 KB
    __shared__ int s_cnt[NSUB];
    const int cblk = blockIdx.x;
    const int tid  = threadIdx.x;
    const int tbeg = cblk * CHUNK;

    if (tid < NSUB) {
        int n = g_count[cblk * NSUB + tid];
        s_cnt[tid] = n < SUBCAP ? n : SUBCAP;
    }

    // Vectorized zero: 8192 float4 / 1024 threads = 8 each
    float4* d4 = (float4*)diff;
    const float4 z = make_float4(0.f, 0.f, 0.f, 0.f);
    #pragma unroll
    for (int i = 0; i < (CHUNK * G_N / 4) / G_N; i++)
        d4[i * G_N + tid] = z;
    __syncthreads();

    #pragma unroll
    for (int s = 0; s < NSUB; s++) {
        const int n = s_cnt[s];
        const int2* lst = &g_list[(cblk * NSUB + s) * SUBCAP];
        for (int i = tid; i < n; i += G_N) {
            int2 ev = lst[i];
            atomicAdd(&diff[(ev.x >> 10) * G_N + (ev.x & (G_N - 1))],
                      __int_as_float(ev.y));
        }
    }
    __syncthreads();

    float acc = g_carry[cblk * G_N + tid];
    #pragma unroll
    for (int r = 0; r < CHUNK; r++) {
        acc += diff[r * G_N + tid];          // row 0 is always 0
        out[(size_t)(tbeg + r) * G_N + tid] = acc;
    }

    __syncthreads();
    if (tid < NSUB) g_count[cblk * NSUB + tid] = 0;  // clean for next replay
}

// ---------------------------------------------------------------------------
extern "C" void kernel_launch(void* const* d_in, const int* in_sizes, int n_in,
                              void* d_out, int out_size) {
    const int*   index    = (const int*)  d_in[0];
    const float* rate     = (const float*)d_in[1];
    const float* start    = (const float*)d_in[2];
    const float* endt     = (const float*)d_in[3];
    const float* t0       = (const float*)d_in[4];
    const int*   group_id = (const int*)  d_in[5];
    const float* weights  = (const float*)d_in[6];
    float* out = (float*)d_out;

    cudaFuncSetAttribute(chunk_emit_kernel,
                         cudaFuncAttributeMaxDynamicSharedMemorySize,
                         CHUNK * G_N * (int)sizeof(float));

    preprocess_kernel<<<E_N / 128, 128>>>(index, rate, start, endt, t0,
                                          group_id, weights);
    chunk_scan_kernel<<<G_N / 64, 64>>>();
    chunk_emit_kernel<<<NCHUNKS, G_N, CHUNK * G_N * (int)sizeof(float)>>>(out);
}